// round 1
// baseline (speedup 1.0000x reference)
#include <cuda_runtime.h>

#define D_MODEL 1024
#define SEQ     2048
#define BATCH   2
#define NHEAD   16
#define DK      64
#define MTOT    (BATCH * SEQ)   // 4096 rows

// Scratch (allocation-free rule: __device__ globals). 4 x 16MB = 64MB.
__device__ float g_Q[BATCH * SEQ * D_MODEL];
__device__ float g_K[BATCH * SEQ * D_MODEL];
__device__ float g_V[BATCH * SEQ * D_MODEL];
__device__ float g_att[BATCH * SEQ * D_MODEL];

// ---------------------------------------------------------------------------
// GEMM: C(MxN) = A(MxK) @ B(KxN), row-major. M%128==0, N%128==0, K%8==0.
// 128x128 block, BK=8, 256 threads, 8x8 per-thread microtile.
// ---------------------------------------------------------------------------
__device__ __forceinline__ void gemm_body(const float* __restrict__ A,
                                          const float* __restrict__ B,
                                          float* __restrict__ C,
                                          int M, int N, int K,
                                          int bm, int bn) {
    __shared__ float As[8][128];
    __shared__ float Bs[8][128];
    const int tid = threadIdx.x;
    const int tx = tid & 15, ty = tid >> 4;

    float acc[8][8] = {};

    const int aRow = tid >> 1;        // 0..127
    const int aCol = (tid & 1) * 4;   // 0 or 4
    const int bRow = tid >> 5;        // 0..7
    const int bCol = (tid & 31) * 4;  // 0..124

    for (int k0 = 0; k0 < K; k0 += 8) {
        float4 av = *(const float4*)(A + (size_t)(bm + aRow) * K + k0 + aCol);
        As[aCol + 0][aRow] = av.x;
        As[aCol + 1][aRow] = av.y;
        As[aCol + 2][aRow] = av.z;
        As[aCol + 3][aRow] = av.w;
        float4 bv = *(const float4*)(B + (size_t)(k0 + bRow) * N + bn + bCol);
        *(float4*)&Bs[bRow][bCol] = bv;
        __syncthreads();

#pragma unroll
        for (int k = 0; k < 8; k++) {
            float a[8], b[8];
            *(float4*)&a[0] = *(const float4*)&As[k][ty * 8];
            *(float4*)&a[4] = *(const float4*)&As[k][ty * 8 + 4];
            *(float4*)&b[0] = *(const float4*)&Bs[k][tx * 8];
            *(float4*)&b[4] = *(const float4*)&Bs[k][tx * 8 + 4];
#pragma unroll
            for (int i = 0; i < 8; i++)
#pragma unroll
                for (int j = 0; j < 8; j++)
                    acc[i][j] = fmaf(a[i], b[j], acc[i][j]);
        }
        __syncthreads();
    }

#pragma unroll
    for (int i = 0; i < 8; i++) {
        float* crow = C + (size_t)(bm + ty * 8 + i) * N + bn + tx * 8;
        *(float4*)(crow)     = make_float4(acc[i][0], acc[i][1], acc[i][2], acc[i][3]);
        *(float4*)(crow + 4) = make_float4(acc[i][4], acc[i][5], acc[i][6], acc[i][7]);
    }
}

// Fused QKV projection: blockIdx.z picks which weight/output.
__global__ __launch_bounds__(256)
void gemm_qkv_kernel(const float* __restrict__ x,
                     const float* __restrict__ Wq,
                     const float* __restrict__ Wk,
                     const float* __restrict__ Wv) {
    const float* W = (blockIdx.z == 0) ? Wq : (blockIdx.z == 1) ? Wk : Wv;
    float* C = (blockIdx.z == 0) ? g_Q : (blockIdx.z == 1) ? g_K : g_V;
    gemm_body(x, W, C, MTOT, D_MODEL, D_MODEL, blockIdx.y * 128, blockIdx.x * 128);
}

// Plain GEMM for the output projection.
__global__ __launch_bounds__(256)
void gemm_kernel(const float* __restrict__ A, const float* __restrict__ B,
                 float* __restrict__ C, int M, int N, int K) {
    gemm_body(A, B, C, M, N, K, blockIdx.y * 128, blockIdx.x * 128);
}

// ---------------------------------------------------------------------------
// Flash-style attention: one CTA = (64-query tile, head, batch).
// 256 threads as 16x16; each thread owns a 4(q) x 4 microtile.
// Online softmax; accumulators in registers; P staged through smem.
// smem: Qs/Ks/Vs/Ps each 64x65 fp32 (pad 65 -> at worst 2-way conflicts).
// ---------------------------------------------------------------------------
#define ATTN_SMEM_FLOATS (4 * 64 * 65)
#define ATTN_SMEM_BYTES  (ATTN_SMEM_FLOATS * 4)

__global__ __launch_bounds__(256)
void attn_kernel(const float* __restrict__ Q, const float* __restrict__ K,
                 const float* __restrict__ V, float* __restrict__ O) {
    extern __shared__ float sm[];
    float (*Qs)[65] = (float(*)[65])(sm);
    float (*Ks)[65] = (float(*)[65])(sm + 64 * 65);
    float (*Vs)[65] = (float(*)[65])(sm + 2 * 64 * 65);
    float (*Ps)[65] = (float(*)[65])(sm + 3 * 64 * 65);

    const int qt = blockIdx.x, h = blockIdx.y, b = blockIdx.z;
    const int tid = threadIdx.x;
    const int tx = tid & 15, ty = tid >> 4;

    const float* Qbase = Q + ((size_t)b * SEQ + qt * 64) * D_MODEL + h * DK;
    const float* Kbase = K + (size_t)b * SEQ * D_MODEL + h * DK;
    const float* Vbase = V + (size_t)b * SEQ * D_MODEL + h * DK;

    // Load Q tile (64 x 64), coalesced gmem float4 reads.
    for (int idx = tid; idx < 64 * 16; idx += 256) {
        int r = idx >> 4, c = (idx & 15) * 4;
        float4 v = *(const float4*)(Qbase + (size_t)r * D_MODEL + c);
        Qs[r][c] = v.x; Qs[r][c + 1] = v.y; Qs[r][c + 2] = v.z; Qs[r][c + 3] = v.w;
    }

    float acc[4][4] = {};
    float m_i[4] = {-1e30f, -1e30f, -1e30f, -1e30f};
    float l_i[4] = {};

    __syncthreads();

    for (int kt = 0; kt < SEQ / 64; kt++) {
        const float* kb = Kbase + (size_t)kt * 64 * D_MODEL;
        const float* vb = Vbase + (size_t)kt * 64 * D_MODEL;
        for (int idx = tid; idx < 64 * 16; idx += 256) {
            int r = idx >> 4, c = (idx & 15) * 4;
            float4 k4 = *(const float4*)(kb + (size_t)r * D_MODEL + c);
            Ks[r][c] = k4.x; Ks[r][c + 1] = k4.y; Ks[r][c + 2] = k4.z; Ks[r][c + 3] = k4.w;
            float4 v4 = *(const float4*)(vb + (size_t)r * D_MODEL + c);
            Vs[r][c] = v4.x; Vs[r][c + 1] = v4.y; Vs[r][c + 2] = v4.z; Vs[r][c + 3] = v4.w;
        }
        __syncthreads();

        // S = Q @ K^T for this 64x64 tile (4x4 per thread)
        float s[4][4] = {};
#pragma unroll 8
        for (int d = 0; d < 64; d++) {
            float qv[4], kv[4];
#pragma unroll
            for (int i = 0; i < 4; i++) qv[i] = Qs[ty * 4 + i][d];
#pragma unroll
            for (int j = 0; j < 4; j++) kv[j] = Ks[tx * 4 + j][d];
#pragma unroll
            for (int i = 0; i < 4; i++)
#pragma unroll
                for (int j = 0; j < 4; j++)
                    s[i][j] = fmaf(qv[i], kv[j], s[i][j]);
        }
        const float scale = 0.125f;  // 1/sqrt(64)
#pragma unroll
        for (int i = 0; i < 4; i++)
#pragma unroll
            for (int j = 0; j < 4; j++)
                s[i][j] *= scale;

        // Online softmax per query row (row spread across 16 tx lanes).
#pragma unroll
        for (int i = 0; i < 4; i++) {
            float mx = fmaxf(fmaxf(s[i][0], s[i][1]), fmaxf(s[i][2], s[i][3]));
            mx = fmaxf(mx, __shfl_xor_sync(0xffffffffu, mx, 1));
            mx = fmaxf(mx, __shfl_xor_sync(0xffffffffu, mx, 2));
            mx = fmaxf(mx, __shfl_xor_sync(0xffffffffu, mx, 4));
            mx = fmaxf(mx, __shfl_xor_sync(0xffffffffu, mx, 8));
            float mn = fmaxf(m_i[i], mx);
            float corr = __expf(m_i[i] - mn);
            m_i[i] = mn;
            float p0 = __expf(s[i][0] - mn);
            float p1 = __expf(s[i][1] - mn);
            float p2 = __expf(s[i][2] - mn);
            float p3 = __expf(s[i][3] - mn);
            float rs = (p0 + p1) + (p2 + p3);
            rs += __shfl_xor_sync(0xffffffffu, rs, 1);
            rs += __shfl_xor_sync(0xffffffffu, rs, 2);
            rs += __shfl_xor_sync(0xffffffffu, rs, 4);
            rs += __shfl_xor_sync(0xffffffffu, rs, 8);
            l_i[i] = l_i[i] * corr + rs;
#pragma unroll
            for (int jd = 0; jd < 4; jd++) acc[i][jd] *= corr;
            Ps[ty * 4 + i][tx * 4 + 0] = p0;
            Ps[ty * 4 + i][tx * 4 + 1] = p1;
            Ps[ty * 4 + i][tx * 4 + 2] = p2;
            Ps[ty * 4 + i][tx * 4 + 3] = p3;
        }
        __syncthreads();

        // O += P @ V  (thread owns q-rows ty*4.. and d-cols tx*4..)
#pragma unroll 8
        for (int j = 0; j < 64; j++) {
            float pv[4], vv[4];
#pragma unroll
            for (int i = 0; i < 4; i++) pv[i] = Ps[ty * 4 + i][j];
#pragma unroll
            for (int jd = 0; jd < 4; jd++) vv[jd] = Vs[j][tx * 4 + jd];
#pragma unroll
            for (int i = 0; i < 4; i++)
#pragma unroll
                for (int jd = 0; jd < 4; jd++)
                    acc[i][jd] = fmaf(pv[i], vv[jd], acc[i][jd]);
        }
        __syncthreads();
    }

    // Normalize and write directly in (B, S, D) concat layout.
    float* obase = O + ((size_t)b * SEQ + qt * 64) * D_MODEL + h * DK;
#pragma unroll
    for (int i = 0; i < 4; i++) {
        float inv = 1.0f / l_i[i];
        float4 v = make_float4(acc[i][0] * inv, acc[i][1] * inv,
                               acc[i][2] * inv, acc[i][3] * inv);
        *(float4*)(obase + (size_t)(ty * 4 + i) * D_MODEL + tx * 4) = v;
    }
}

// ---------------------------------------------------------------------------
extern "C" void kernel_launch(void* const* d_in, const int* in_sizes, int n_in,
                              void* d_out, int out_size) {
    const float* x  = (const float*)d_in[0];
    const float* Wq = (const float*)d_in[1];
    const float* Wk = (const float*)d_in[2];
    const float* Wv = (const float*)d_in[3];
    const float* Wo = (const float*)d_in[4];
    float* out = (float*)d_out;

    float *Qp, *Kp, *Vp, *Ap;
    cudaGetSymbolAddress((void**)&Qp, g_Q);
    cudaGetSymbolAddress((void**)&Kp, g_K);
    cudaGetSymbolAddress((void**)&Vp, g_V);
    cudaGetSymbolAddress((void**)&Ap, g_att);

    // Fused QKV projections: grid (N/128, M/128, 3) = (8, 32, 3) = 768 CTAs
    dim3 qkv_grid(D_MODEL / 128, MTOT / 128, 3);
    gemm_qkv_kernel<<<qkv_grid, 256>>>(x, Wq, Wk, Wv);

    // Attention: grid (32 q-tiles, 16 heads, 2 batch) = 1024 CTAs
    cudaFuncSetAttribute(attn_kernel, cudaFuncAttributeMaxDynamicSharedMemorySize,
                         ATTN_SMEM_BYTES);
    attn_kernel<<<dim3(SEQ / 64, NHEAD, BATCH), 256, ATTN_SMEM_BYTES>>>(Qp, Kp, Vp, Ap);

    // Output projection
    dim3 o_grid(D_MODEL / 128, MTOT / 128);
    gemm_kernel<<<o_grid, 256>>>(Ap, Wo, out, MTOT, D_MODEL, D_MODEL);
}

// round 2
// speedup vs baseline: 4.8771x; 4.8771x over previous
#include <cuda_runtime.h>
#include <cstdint>

#define D_MODEL 1024
#define SEQ     2048
#define BATCH   2
#define NHEAD   16
#define DK      64
#define MTOT    (BATCH * SEQ)

// Scratch (allocation-free rule)
__device__ float g_Q[BATCH * SEQ * D_MODEL];
__device__ float g_K[BATCH * SEQ * D_MODEL];
__device__ float g_V[BATCH * SEQ * D_MODEL];
__device__ float g_att[BATCH * SEQ * D_MODEL];

// ---------------------------------------------------------------------------
// helpers
// ---------------------------------------------------------------------------
__device__ __forceinline__ uint32_t f2tf(float f) {
    uint32_t u;
    asm("cvt.rna.tf32.f32 %0, %1;" : "=r"(u) : "f"(f));
    return u;
}

__device__ __forceinline__ void mma_tf32(float* d, const uint32_t* a,
                                         const uint32_t* b, const float* c) {
    asm volatile(
        "mma.sync.aligned.m16n8k8.row.col.f32.tf32.tf32.f32 "
        "{%0,%1,%2,%3}, {%4,%5,%6,%7}, {%8,%9}, {%10,%11,%12,%13};\n"
        : "=f"(d[0]), "=f"(d[1]), "=f"(d[2]), "=f"(d[3])
        : "r"(a[0]), "r"(a[1]), "r"(a[2]), "r"(a[3]),
          "r"(b[0]), "r"(b[1]),
          "f"(c[0]), "f"(c[1]), "f"(c[2]), "f"(c[3]));
}

// ---------------------------------------------------------------------------
// TF32 GEMM: C(MxN) = A(MxK) @ B(KxN), row-major, tiles 128x128x16.
// 256 threads = 8 warps, warp grid 4(m) x 2(n), warp tile 32x64.
// ---------------------------------------------------------------------------
__device__ __forceinline__ void gemm_tf32_body(const float* __restrict__ A,
                                               const float* __restrict__ B,
                                               float* __restrict__ C,
                                               int M, int N, int K,
                                               int bm, int bn) {
    __shared__ uint32_t As[128][20];   // pad 20: A-frag LDS conflict-free
    __shared__ uint32_t Bs[16][136];   // pad 136: B-frag LDS conflict-free

    const int tid = threadIdx.x;
    const int w = tid >> 5, lane = tid & 31;
    const int wr = w >> 1, wc = w & 1;
    const int gid = lane >> 2, tig = lane & 3;

    float acc[2][8][4] = {};

    for (int k0 = 0; k0 < K; k0 += 16) {
#pragma unroll
        for (int p = 0; p < 2; p++) {
            int idx = p * 256 + tid;                 // 0..511
            int ar = idx >> 2, ac = (idx & 3) * 4;   // A: 128 rows x 16 cols
            float4 av = *(const float4*)(A + (size_t)(bm + ar) * K + k0 + ac);
            uint4 au = make_uint4(f2tf(av.x), f2tf(av.y), f2tf(av.z), f2tf(av.w));
            *(uint4*)&As[ar][ac] = au;
            int br = idx >> 5, bc = (idx & 31) * 4;  // B: 16 rows x 128 cols
            float4 bv = *(const float4*)(B + (size_t)(k0 + br) * N + bn + bc);
            uint4 bu = make_uint4(f2tf(bv.x), f2tf(bv.y), f2tf(bv.z), f2tf(bv.w));
            *(uint4*)&Bs[br][bc] = bu;
        }
        __syncthreads();

#pragma unroll
        for (int kk = 0; kk < 16; kk += 8) {
            uint32_t af[2][4];
#pragma unroll
            for (int mt = 0; mt < 2; mt++) {
                int r0 = wr * 32 + mt * 16 + gid;
                af[mt][0] = As[r0][kk + tig];
                af[mt][1] = As[r0 + 8][kk + tig];
                af[mt][2] = As[r0][kk + tig + 4];
                af[mt][3] = As[r0 + 8][kk + tig + 4];
            }
            uint32_t bf[8][2];
#pragma unroll
            for (int nt = 0; nt < 8; nt++) {
                int cb = wc * 64 + nt * 8 + gid;
                bf[nt][0] = Bs[kk + tig][cb];
                bf[nt][1] = Bs[kk + tig + 4][cb];
            }
#pragma unroll
            for (int mt = 0; mt < 2; mt++)
#pragma unroll
                for (int nt = 0; nt < 8; nt++)
                    mma_tf32(acc[mt][nt], af[mt], bf[nt], acc[mt][nt]);
        }
        __syncthreads();
    }

#pragma unroll
    for (int mt = 0; mt < 2; mt++)
#pragma unroll
        for (int nt = 0; nt < 8; nt++) {
            int row = bm + wr * 32 + mt * 16 + gid;
            int col = bn + wc * 64 + nt * 8 + 2 * tig;
            *(float2*)(C + (size_t)row * N + col) =
                make_float2(acc[mt][nt][0], acc[mt][nt][1]);
            *(float2*)(C + (size_t)(row + 8) * N + col) =
                make_float2(acc[mt][nt][2], acc[mt][nt][3]);
        }
}

__global__ __launch_bounds__(256)
void gemm_qkv_kernel(const float* __restrict__ x,
                     const float* __restrict__ Wq,
                     const float* __restrict__ Wk,
                     const float* __restrict__ Wv) {
    const float* W = (blockIdx.z == 0) ? Wq : (blockIdx.z == 1) ? Wk : Wv;
    float* C = (blockIdx.z == 0) ? g_Q : (blockIdx.z == 1) ? g_K : g_V;
    gemm_tf32_body(x, W, C, MTOT, D_MODEL, D_MODEL,
                   blockIdx.y * 128, blockIdx.x * 128);
}

__global__ __launch_bounds__(256)
void gemm_kernel(const float* __restrict__ A, const float* __restrict__ B,
                 float* __restrict__ C, int M, int N, int K) {
    gemm_tf32_body(A, B, C, M, N, K, blockIdx.y * 128, blockIdx.x * 128);
}

// ---------------------------------------------------------------------------
// Flash attention with TF32 mma. CTA = (64 q, head, batch), 128 threads.
// Each warp: 16 q rows x full 64-wide kv tile (1 m-tile x 8 n-tiles).
// smem (dynamic): Qs[64][68], Ks[64][68], Ps[64][68], Vs[64][72] (uint tf32)
// ---------------------------------------------------------------------------
#define QS_STRIDE 68
#define VS_STRIDE 72
#define SM_Q 0
#define SM_K (64 * QS_STRIDE)
#define SM_P (2 * 64 * QS_STRIDE)
#define SM_V (3 * 64 * QS_STRIDE)
#define ATTN_SMEM_UINTS (3 * 64 * QS_STRIDE + 64 * VS_STRIDE)
#define ATTN_SMEM_BYTES (ATTN_SMEM_UINTS * 4)

__global__ __launch_bounds__(128)
void attn_kernel(const float* __restrict__ Q, const float* __restrict__ K,
                 const float* __restrict__ V, float* __restrict__ O) {
    extern __shared__ uint32_t sm[];
    uint32_t* Qs = sm + SM_Q;
    uint32_t* Ks = sm + SM_K;
    uint32_t* Ps = sm + SM_P;
    uint32_t* Vs = sm + SM_V;

    const int qt = blockIdx.x, h = blockIdx.y, b = blockIdx.z;
    const int tid = threadIdx.x;
    const int w = tid >> 5, lane = tid & 31;
    const int gid = lane >> 2, tig = lane & 3;

    const float* Qbase = Q + ((size_t)b * SEQ + qt * 64) * D_MODEL + h * DK;
    const float* Kbase = K + (size_t)b * SEQ * D_MODEL + h * DK;
    const float* Vbase = V + (size_t)b * SEQ * D_MODEL + h * DK;

    // Load + convert Q tile (64x64)
#pragma unroll
    for (int i = 0; i < 8; i++) {
        int idx = i * 128 + tid;
        int r = idx >> 4, c = (idx & 15) * 4;
        float4 v = *(const float4*)(Qbase + (size_t)r * D_MODEL + c);
        *(uint4*)&Qs[r * QS_STRIDE + c] =
            make_uint4(f2tf(v.x), f2tf(v.y), f2tf(v.z), f2tf(v.w));
    }
    __syncthreads();

    // Hoist Q fragments (warp's 16 rows, all 8 k-chunks)
    const int r0 = w * 16 + gid;
    uint32_t qf[8][4];
#pragma unroll
    for (int kc = 0; kc < 8; kc++) {
        qf[kc][0] = Qs[r0 * QS_STRIDE + kc * 8 + tig];
        qf[kc][1] = Qs[(r0 + 8) * QS_STRIDE + kc * 8 + tig];
        qf[kc][2] = Qs[r0 * QS_STRIDE + kc * 8 + tig + 4];
        qf[kc][3] = Qs[(r0 + 8) * QS_STRIDE + kc * 8 + tig + 4];
    }

    float o[8][4] = {};
    float m0 = -1e30f, m1 = -1e30f, l0 = 0.f, l1 = 0.f;

    for (int kt = 0; kt < SEQ / 64; kt++) {
        __syncthreads();  // previous PV done with Vs / S done with Ks
        const float* kb = Kbase + (size_t)kt * 64 * D_MODEL;
        const float* vb = Vbase + (size_t)kt * 64 * D_MODEL;
#pragma unroll
        for (int i = 0; i < 8; i++) {
            int idx = i * 128 + tid;
            int r = idx >> 4, c = (idx & 15) * 4;
            float4 k4 = *(const float4*)(kb + (size_t)r * D_MODEL + c);
            *(uint4*)&Ks[r * QS_STRIDE + c] =
                make_uint4(f2tf(k4.x), f2tf(k4.y), f2tf(k4.z), f2tf(k4.w));
            float4 v4 = *(const float4*)(vb + (size_t)r * D_MODEL + c);
            *(uint4*)&Vs[r * VS_STRIDE + c] =
                make_uint4(f2tf(v4.x), f2tf(v4.y), f2tf(v4.z), f2tf(v4.w));
        }
        __syncthreads();

        // S = Q @ K^T  (16 x 64 per warp)
        float s[8][4] = {};
#pragma unroll
        for (int kc = 0; kc < 8; kc++) {
#pragma unroll
            for (int nt = 0; nt < 8; nt++) {
                uint32_t kf[2];
                int kvp = nt * 8 + gid;  // kv position in tile (= mma col)
                kf[0] = Ks[kvp * QS_STRIDE + kc * 8 + tig];
                kf[1] = Ks[kvp * QS_STRIDE + kc * 8 + tig + 4];
                mma_tf32(s[nt], qf[kc], kf, s[nt]);
            }
        }

        const float scale = 0.125f;  // 1/sqrt(64)
        float mx0 = -1e30f, mx1 = -1e30f;
#pragma unroll
        for (int nt = 0; nt < 8; nt++) {
#pragma unroll
            for (int i = 0; i < 4; i++) s[nt][i] *= scale;
            mx0 = fmaxf(mx0, fmaxf(s[nt][0], s[nt][1]));
            mx1 = fmaxf(mx1, fmaxf(s[nt][2], s[nt][3]));
        }
        mx0 = fmaxf(mx0, __shfl_xor_sync(0xffffffffu, mx0, 1));
        mx0 = fmaxf(mx0, __shfl_xor_sync(0xffffffffu, mx0, 2));
        mx1 = fmaxf(mx1, __shfl_xor_sync(0xffffffffu, mx1, 1));
        mx1 = fmaxf(mx1, __shfl_xor_sync(0xffffffffu, mx1, 2));

        float nm0 = fmaxf(m0, mx0), nm1 = fmaxf(m1, mx1);
        float corr0 = __expf(m0 - nm0), corr1 = __expf(m1 - nm1);
        m0 = nm0; m1 = nm1;

        float rs0 = 0.f, rs1 = 0.f;
#pragma unroll
        for (int nt = 0; nt < 8; nt++) {
            float p0 = __expf(s[nt][0] - nm0);
            float p1 = __expf(s[nt][1] - nm0);
            float p2 = __expf(s[nt][2] - nm1);
            float p3 = __expf(s[nt][3] - nm1);
            rs0 += p0 + p1;
            rs1 += p2 + p3;
            int col = nt * 8 + 2 * tig;
            *(uint2*)&Ps[r0 * QS_STRIDE + col] = make_uint2(f2tf(p0), f2tf(p1));
            *(uint2*)&Ps[(r0 + 8) * QS_STRIDE + col] = make_uint2(f2tf(p2), f2tf(p3));
        }
        rs0 += __shfl_xor_sync(0xffffffffu, rs0, 1);
        rs0 += __shfl_xor_sync(0xffffffffu, rs0, 2);
        rs1 += __shfl_xor_sync(0xffffffffu, rs1, 1);
        rs1 += __shfl_xor_sync(0xffffffffu, rs1, 2);
        l0 = l0 * corr0 + rs0;
        l1 = l1 * corr1 + rs1;

#pragma unroll
        for (int nt = 0; nt < 8; nt++) {
            o[nt][0] *= corr0; o[nt][1] *= corr0;
            o[nt][2] *= corr1; o[nt][3] *= corr1;
        }
        __syncwarp();  // P rows are warp-private; order STS -> LDS

        // O += P @ V  (16 x 64 per warp, k over 64 kv positions)
#pragma unroll
        for (int kc = 0; kc < 8; kc++) {
            uint32_t pa[4];
            pa[0] = Ps[r0 * QS_STRIDE + kc * 8 + tig];
            pa[1] = Ps[(r0 + 8) * QS_STRIDE + kc * 8 + tig];
            pa[2] = Ps[r0 * QS_STRIDE + kc * 8 + tig + 4];
            pa[3] = Ps[(r0 + 8) * QS_STRIDE + kc * 8 + tig + 4];
#pragma unroll
            for (int nt = 0; nt < 8; nt++) {
                uint32_t vf[2];
                vf[0] = Vs[(kc * 8 + tig) * VS_STRIDE + nt * 8 + gid];
                vf[1] = Vs[(kc * 8 + tig + 4) * VS_STRIDE + nt * 8 + gid];
                mma_tf32(o[nt], pa, vf, o[nt]);
            }
        }
    }

    // Normalize and write to concat layout (B, S, D)
    float inv0 = 1.0f / l0, inv1 = 1.0f / l1;
    float* obase = O + ((size_t)b * SEQ + qt * 64) * D_MODEL + h * DK;
#pragma unroll
    for (int nt = 0; nt < 8; nt++) {
        int col = nt * 8 + 2 * tig;
        *(float2*)(obase + (size_t)r0 * D_MODEL + col) =
            make_float2(o[nt][0] * inv0, o[nt][1] * inv0);
        *(float2*)(obase + (size_t)(r0 + 8) * D_MODEL + col) =
            make_float2(o[nt][2] * inv1, o[nt][3] * inv1);
    }
}

// ---------------------------------------------------------------------------
extern "C" void kernel_launch(void* const* d_in, const int* in_sizes, int n_in,
                              void* d_out, int out_size) {
    const float* x  = (const float*)d_in[0];
    const float* Wq = (const float*)d_in[1];
    const float* Wk = (const float*)d_in[2];
    const float* Wv = (const float*)d_in[3];
    const float* Wo = (const float*)d_in[4];
    float* out = (float*)d_out;

    float *Qp, *Kp, *Vp, *Ap;
    cudaGetSymbolAddress((void**)&Qp, g_Q);
    cudaGetSymbolAddress((void**)&Kp, g_K);
    cudaGetSymbolAddress((void**)&Vp, g_V);
    cudaGetSymbolAddress((void**)&Ap, g_att);

    dim3 qkv_grid(D_MODEL / 128, MTOT / 128, 3);
    gemm_qkv_kernel<<<qkv_grid, 256>>>(x, Wq, Wk, Wv);

    cudaFuncSetAttribute(attn_kernel, cudaFuncAttributeMaxDynamicSharedMemorySize,
                         ATTN_SMEM_BYTES);
    attn_kernel<<<dim3(SEQ / 64, NHEAD, BATCH), 128, ATTN_SMEM_BYTES>>>(Qp, Kp, Vp, Ap);

    dim3 o_grid(D_MODEL / 128, MTOT / 128);
    gemm_kernel<<<o_grid, 256>>>(Ap, Wo, out, MTOT, D_MODEL, D_MODEL);
}

// round 3
// speedup vs baseline: 5.4029x; 1.1078x over previous
#include <cuda_runtime.h>
#include <cstdint>

#define D_MODEL 1024
#define SEQ     2048
#define BATCH   2
#define NHEAD   16
#define DK      64
#define MTOT    (BATCH * SEQ)

// Scratch (allocation-free rule)
__device__ float g_Q[BATCH * SEQ * D_MODEL];
__device__ float g_K[BATCH * SEQ * D_MODEL];
__device__ float g_V[BATCH * SEQ * D_MODEL];
__device__ float g_att[BATCH * SEQ * D_MODEL];

// ---------------------------------------------------------------------------
__device__ __forceinline__ uint32_t f2tf(float f) {
    uint32_t u;
    asm("cvt.rna.tf32.f32 %0, %1;" : "=r"(u) : "f"(f));
    return u;
}

__device__ __forceinline__ void mma_tf32(float* d, const uint32_t* a,
                                         const uint32_t* b, const float* c) {
    asm volatile(
        "mma.sync.aligned.m16n8k8.row.col.f32.tf32.tf32.f32 "
        "{%0,%1,%2,%3}, {%4,%5,%6,%7}, {%8,%9}, {%10,%11,%12,%13};\n"
        : "=f"(d[0]), "=f"(d[1]), "=f"(d[2]), "=f"(d[3])
        : "r"(a[0]), "r"(a[1]), "r"(a[2]), "r"(a[3]),
          "r"(b[0]), "r"(b[1]),
          "f"(c[0]), "f"(c[1]), "f"(c[2]), "f"(c[3]));
}

// ---------------------------------------------------------------------------
// TF32 GEMM, 128x128x16 tiles, 8 warps (4m x 2n), warp tile 32x64.
// Software-pipelined double-buffered smem: ldg(next) | mma(cur) | sts(next).
// ---------------------------------------------------------------------------
__device__ __forceinline__ void gemm_tf32_body(const float* __restrict__ A,
                                               const float* __restrict__ B,
                                               float* __restrict__ C,
                                               int M, int N, int K,
                                               int bm, int bn) {
    __shared__ uint32_t As[2][128][20];
    __shared__ uint32_t Bs[2][16][136];

    const int tid = threadIdx.x;
    const int w = tid >> 5, lane = tid & 31;
    const int wr = w >> 1, wc = w & 1;
    const int gid = lane >> 2, tig = lane & 3;

    float acc[2][8][4] = {};
    float4 avr[2], bvr[2];

    // load indices (idx = p*256 + tid, p in {0,1})
    const int ar0 = tid >> 2, ac0 = (tid & 3) * 4;            // p=0 A
    const int ar1 = (256 + tid) >> 2, ac1 = ac0;              // p=1 A
    const int br0 = tid >> 5, bc0 = (tid & 31) * 4;           // p=0 B
    const int br1 = (256 + tid) >> 5, bc1 = bc0;              // p=1 B

    auto load_regs = [&](int k0) {
        avr[0] = *(const float4*)(A + (size_t)(bm + ar0) * K + k0 + ac0);
        avr[1] = *(const float4*)(A + (size_t)(bm + ar1) * K + k0 + ac1);
        bvr[0] = *(const float4*)(B + (size_t)(k0 + br0) * N + bn + bc0);
        bvr[1] = *(const float4*)(B + (size_t)(k0 + br1) * N + bn + bc1);
    };
    auto store_smem = [&](int buf) {
        *(uint4*)&As[buf][ar0][ac0] =
            make_uint4(f2tf(avr[0].x), f2tf(avr[0].y), f2tf(avr[0].z), f2tf(avr[0].w));
        *(uint4*)&As[buf][ar1][ac1] =
            make_uint4(f2tf(avr[1].x), f2tf(avr[1].y), f2tf(avr[1].z), f2tf(avr[1].w));
        *(uint4*)&Bs[buf][br0][bc0] =
            make_uint4(f2tf(bvr[0].x), f2tf(bvr[0].y), f2tf(bvr[0].z), f2tf(bvr[0].w));
        *(uint4*)&Bs[buf][br1][bc1] =
            make_uint4(f2tf(bvr[1].x), f2tf(bvr[1].y), f2tf(bvr[1].z), f2tf(bvr[1].w));
    };

    load_regs(0);
    store_smem(0);
    __syncthreads();

    int buf = 0;
    for (int k0 = 0; k0 < K; k0 += 16, buf ^= 1) {
        const bool more = (k0 + 16) < K;
        if (more) load_regs(k0 + 16);

#pragma unroll
        for (int kk = 0; kk < 16; kk += 8) {
            uint32_t af[2][4];
#pragma unroll
            for (int mt = 0; mt < 2; mt++) {
                int r0 = wr * 32 + mt * 16 + gid;
                af[mt][0] = As[buf][r0][kk + tig];
                af[mt][1] = As[buf][r0 + 8][kk + tig];
                af[mt][2] = As[buf][r0][kk + tig + 4];
                af[mt][3] = As[buf][r0 + 8][kk + tig + 4];
            }
            uint32_t bf[8][2];
#pragma unroll
            for (int nt = 0; nt < 8; nt++) {
                int cb = wc * 64 + nt * 8 + gid;
                bf[nt][0] = Bs[buf][kk + tig][cb];
                bf[nt][1] = Bs[buf][kk + tig + 4][cb];
            }
#pragma unroll
            for (int mt = 0; mt < 2; mt++)
#pragma unroll
                for (int nt = 0; nt < 8; nt++)
                    mma_tf32(acc[mt][nt], af[mt], bf[nt], acc[mt][nt]);
        }

        if (more) {
            store_smem(buf ^ 1);
            __syncthreads();
        }
    }

#pragma unroll
    for (int mt = 0; mt < 2; mt++)
#pragma unroll
        for (int nt = 0; nt < 8; nt++) {
            int row = bm + wr * 32 + mt * 16 + gid;
            int col = bn + wc * 64 + nt * 8 + 2 * tig;
            *(float2*)(C + (size_t)row * N + col) =
                make_float2(acc[mt][nt][0], acc[mt][nt][1]);
            *(float2*)(C + (size_t)(row + 8) * N + col) =
                make_float2(acc[mt][nt][2], acc[mt][nt][3]);
        }
}

__global__ __launch_bounds__(256)
void gemm_qkv_kernel(const float* __restrict__ x,
                     const float* __restrict__ Wq,
                     const float* __restrict__ Wk,
                     const float* __restrict__ Wv) {
    const float* W = (blockIdx.z == 0) ? Wq : (blockIdx.z == 1) ? Wk : Wv;
    float* C = (blockIdx.z == 0) ? g_Q : (blockIdx.z == 1) ? g_K : g_V;
    gemm_tf32_body(x, W, C, MTOT, D_MODEL, D_MODEL,
                   blockIdx.y * 128, blockIdx.x * 128);
}

__global__ __launch_bounds__(256)
void gemm_kernel(const float* __restrict__ A, const float* __restrict__ B,
                 float* __restrict__ C, int M, int N, int K) {
    gemm_tf32_body(A, B, C, M, N, K, blockIdx.y * 128, blockIdx.x * 128);
}

// ---------------------------------------------------------------------------
// Flash attention, TF32 mma. CTA = (128 q rows, head, batch), 256 threads.
// Warp w owns q rows [w*16, w*16+16). kv tiles of 64.
// smem: Qs[128][68] (reused as Ps after Q-fragment hoist), Ks[64][68], Vs[64][72].
// ---------------------------------------------------------------------------
#define QS_STRIDE 68
#define VS_STRIDE 72
#define SM_Q 0
#define SM_K (128 * QS_STRIDE)
#define SM_V (SM_K + 64 * QS_STRIDE)
#define ATTN_SMEM_UINTS (SM_V + 64 * VS_STRIDE)
#define ATTN_SMEM_BYTES (ATTN_SMEM_UINTS * 4)

__global__ __launch_bounds__(256)
void attn_kernel(const float* __restrict__ Q, const float* __restrict__ K,
                 const float* __restrict__ V, float* __restrict__ O) {
    extern __shared__ uint32_t sm[];
    uint32_t* Qs = sm + SM_Q;   // 128 x 68
    uint32_t* Ps = sm + SM_Q;   // aliased: Qs dead after fragment hoist
    uint32_t* Ks = sm + SM_K;   // 64 x 68
    uint32_t* Vs = sm + SM_V;   // 64 x 72

    const int qt = blockIdx.x, h = blockIdx.y, b = blockIdx.z;
    const int tid = threadIdx.x;
    const int w = tid >> 5, lane = tid & 31;
    const int gid = lane >> 2, tig = lane & 3;

    const float* Qbase = Q + ((size_t)b * SEQ + qt * 128) * D_MODEL + h * DK;
    const float* Kbase = K + (size_t)b * SEQ * D_MODEL + h * DK;
    const float* Vbase = V + (size_t)b * SEQ * D_MODEL + h * DK;

    // Load + convert Q tile (128 x 64)
#pragma unroll
    for (int i = 0; i < 8; i++) {
        int idx = i * 256 + tid;
        int r = idx >> 4, c = (idx & 15) * 4;
        float4 v = *(const float4*)(Qbase + (size_t)r * D_MODEL + c);
        *(uint4*)&Qs[r * QS_STRIDE + c] =
            make_uint4(f2tf(v.x), f2tf(v.y), f2tf(v.z), f2tf(v.w));
    }
    __syncthreads();

    // Hoist Q fragments (warp's 16 rows, 8 k-chunks). Qs smem dead after this.
    const int r0 = w * 16 + gid;
    uint32_t qf[8][4];
#pragma unroll
    for (int kc = 0; kc < 8; kc++) {
        qf[kc][0] = Qs[r0 * QS_STRIDE + kc * 8 + tig];
        qf[kc][1] = Qs[(r0 + 8) * QS_STRIDE + kc * 8 + tig];
        qf[kc][2] = Qs[r0 * QS_STRIDE + kc * 8 + tig + 4];
        qf[kc][3] = Qs[(r0 + 8) * QS_STRIDE + kc * 8 + tig + 4];
    }

    float o[8][4] = {};
    float m0 = -1e30f, m1 = -1e30f, l0 = 0.f, l1 = 0.f;

    for (int kt = 0; kt < SEQ / 64; kt++) {
        __syncthreads();  // all warps done with Ks (S) / Vs (PV) / Ps-region of prev iter
        const float* kb = Kbase + (size_t)kt * 64 * D_MODEL;
        const float* vb = Vbase + (size_t)kt * 64 * D_MODEL;
#pragma unroll
        for (int i = 0; i < 4; i++) {
            int idx = i * 256 + tid;
            int r = idx >> 4, c = (idx & 15) * 4;
            float4 k4 = *(const float4*)(kb + (size_t)r * D_MODEL + c);
            *(uint4*)&Ks[r * QS_STRIDE + c] =
                make_uint4(f2tf(k4.x), f2tf(k4.y), f2tf(k4.z), f2tf(k4.w));
            float4 v4 = *(const float4*)(vb + (size_t)r * D_MODEL + c);
            *(uint4*)&Vs[r * VS_STRIDE + c] =
                make_uint4(f2tf(v4.x), f2tf(v4.y), f2tf(v4.z), f2tf(v4.w));
        }
        __syncthreads();

        // S = Q @ K^T  (16 x 64 per warp)
        float s[8][4] = {};
#pragma unroll
        for (int kc = 0; kc < 8; kc++) {
#pragma unroll
            for (int nt = 0; nt < 8; nt++) {
                uint32_t kf[2];
                int kvp = nt * 8 + gid;
                kf[0] = Ks[kvp * QS_STRIDE + kc * 8 + tig];
                kf[1] = Ks[kvp * QS_STRIDE + kc * 8 + tig + 4];
                mma_tf32(s[nt], qf[kc], kf, s[nt]);
            }
        }

        const float scale = 0.125f;  // 1/sqrt(64)
        float mx0 = -1e30f, mx1 = -1e30f;
#pragma unroll
        for (int nt = 0; nt < 8; nt++) {
#pragma unroll
            for (int i = 0; i < 4; i++) s[nt][i] *= scale;
            mx0 = fmaxf(mx0, fmaxf(s[nt][0], s[nt][1]));
            mx1 = fmaxf(mx1, fmaxf(s[nt][2], s[nt][3]));
        }
        mx0 = fmaxf(mx0, __shfl_xor_sync(0xffffffffu, mx0, 1));
        mx0 = fmaxf(mx0, __shfl_xor_sync(0xffffffffu, mx0, 2));
        mx1 = fmaxf(mx1, __shfl_xor_sync(0xffffffffu, mx1, 1));
        mx1 = fmaxf(mx1, __shfl_xor_sync(0xffffffffu, mx1, 2));

        float nm0 = fmaxf(m0, mx0), nm1 = fmaxf(m1, mx1);
        float corr0 = __expf(m0 - nm0), corr1 = __expf(m1 - nm1);
        m0 = nm0; m1 = nm1;

        float rs0 = 0.f, rs1 = 0.f;
#pragma unroll
        for (int nt = 0; nt < 8; nt++) {
            float p0 = __expf(s[nt][0] - nm0);
            float p1 = __expf(s[nt][1] - nm0);
            float p2 = __expf(s[nt][2] - nm1);
            float p3 = __expf(s[nt][3] - nm1);
            rs0 += p0 + p1;
            rs1 += p2 + p3;
            int col = nt * 8 + 2 * tig;
            *(uint2*)&Ps[r0 * QS_STRIDE + col] = make_uint2(f2tf(p0), f2tf(p1));
            *(uint2*)&Ps[(r0 + 8) * QS_STRIDE + col] = make_uint2(f2tf(p2), f2tf(p3));
        }
        rs0 += __shfl_xor_sync(0xffffffffu, rs0, 1);
        rs0 += __shfl_xor_sync(0xffffffffu, rs0, 2);
        rs1 += __shfl_xor_sync(0xffffffffu, rs1, 1);
        rs1 += __shfl_xor_sync(0xffffffffu, rs1, 2);
        l0 = l0 * corr0 + rs0;
        l1 = l1 * corr1 + rs1;

#pragma unroll
        for (int nt = 0; nt < 8; nt++) {
            o[nt][0] *= corr0; o[nt][1] *= corr0;
            o[nt][2] *= corr1; o[nt][3] *= corr1;
        }
        __syncwarp();  // Ps rows are warp-private; order STS -> LDS

        // O += P @ V
#pragma unroll
        for (int kc = 0; kc < 8; kc++) {
            uint32_t pa[4];
            pa[0] = Ps[r0 * QS_STRIDE + kc * 8 + tig];
            pa[1] = Ps[(r0 + 8) * QS_STRIDE + kc * 8 + tig];
            pa[2] = Ps[r0 * QS_STRIDE + kc * 8 + tig + 4];
            pa[3] = Ps[(r0 + 8) * QS_STRIDE + kc * 8 + tig + 4];
#pragma unroll
            for (int nt = 0; nt < 8; nt++) {
                uint32_t vf[2];
                vf[0] = Vs[(kc * 8 + tig) * VS_STRIDE + nt * 8 + gid];
                vf[1] = Vs[(kc * 8 + tig + 4) * VS_STRIDE + nt * 8 + gid];
                mma_tf32(o[nt], pa, vf, o[nt]);
            }
        }
    }

    // Normalize and write concat layout (B, S, D)
    float inv0 = 1.0f / l0, inv1 = 1.0f / l1;
    float* obase = O + ((size_t)b * SEQ + qt * 128) * D_MODEL + h * DK;
#pragma unroll
    for (int nt = 0; nt < 8; nt++) {
        int col = nt * 8 + 2 * tig;
        *(float2*)(obase + (size_t)r0 * D_MODEL + col) =
            make_float2(o[nt][0] * inv0, o[nt][1] * inv0);
        *(float2*)(obase + (size_t)(r0 + 8) * D_MODEL + col) =
            make_float2(o[nt][2] * inv1, o[nt][3] * inv1);
    }
}

// ---------------------------------------------------------------------------
extern "C" void kernel_launch(void* const* d_in, const int* in_sizes, int n_in,
                              void* d_out, int out_size) {
    const float* x  = (const float*)d_in[0];
    const float* Wq = (const float*)d_in[1];
    const float* Wk = (const float*)d_in[2];
    const float* Wv = (const float*)d_in[3];
    const float* Wo = (const float*)d_in[4];
    float* out = (float*)d_out;

    float *Qp, *Kp, *Vp, *Ap;
    cudaGetSymbolAddress((void**)&Qp, g_Q);
    cudaGetSymbolAddress((void**)&Kp, g_K);
    cudaGetSymbolAddress((void**)&Vp, g_V);
    cudaGetSymbolAddress((void**)&Ap, g_att);

    dim3 qkv_grid(D_MODEL / 128, MTOT / 128, 3);
    gemm_qkv_kernel<<<qkv_grid, 256>>>(x, Wq, Wk, Wv);

    cudaFuncSetAttribute(attn_kernel, cudaFuncAttributeMaxDynamicSharedMemorySize,
                         ATTN_SMEM_BYTES);
    attn_kernel<<<dim3(SEQ / 128, NHEAD, BATCH), 256, ATTN_SMEM_BYTES>>>(Qp, Kp, Vp, Ap);

    dim3 o_grid(D_MODEL / 128, MTOT / 128);
    gemm_kernel<<<o_grid, 256>>>(Ap, Wo, out, MTOT, D_MODEL, D_MODEL);
}